// round 14
// baseline (speedup 1.0000x reference)
#include <cuda_runtime.h>

// B=8192, D=512, NUM_CLASSES=90, K=8
// Numerics (validated R9+): NEON VF4xIC2 dot structure:
//   8 serial FMA chains, chain j covers elements 8i+j; combine
//   v_e = fadd(chain_e, chain_{e+4}); dot = fadd(fadd(v0,v1),fadd(v2,v3));
//   d = fadd(1,dot). Epilogue f32 per-op rounded, k ascending. Batch sums double.
// R14: x bulk-staged to SMEM (high-MLP burst) -> chain is pure LDS+FMA;
// conflict-free pads; S=2 interleave; shfl epilogue; fused final reduction.

#define NUM_CLASSES 90
#define CHUNKS      16
#define CHUNK_B     512
#define NBLK        (NUM_CLASSES * CHUNKS)   // 1440
#define THREADS     96
#define NWARPS      3
#define NGROUPS     6
#define NS          12                        // x slots per round (= 2*NGROUPS)
#define CPAD        520
#define XPAD        520

__device__ double   g_partials[NBLK];
__device__ unsigned g_count = 0;

__global__ __launch_bounds__(THREADS) void loss_main(
    const float* __restrict__ x,
    const float* __restrict__ centers,
    const int* __restrict__ labels,
    float* __restrict__ out)
{
    __shared__ float    cs[8 * CPAD];        // 16.6 KB
    __shared__ float    xsm[NS * XPAD];      // 25.0 KB
    __shared__ int      list[CHUNK_B];       // 2 KB
    __shared__ unsigned gmask[16];
    __shared__ int      gbase[16];
    __shared__ int      s_n;
    __shared__ double   red[NWARPS];
    __shared__ int      s_last;

    const int tid    = threadIdx.x;
    const int cls    = blockIdx.x / CHUNKS;
    const int chunk  = blockIdx.x % CHUNKS;
    const int base_b = chunk * CHUNK_B;
    const int warp   = tid >> 5;
    const int lane   = tid & 31;

    // ---- stage this class's 8 center rows (coalesced float4 burst) ----
    const float4* __restrict__ gc4 =
        reinterpret_cast<const float4*>(centers + (size_t)cls * 8 * 512);
    for (int u = tid; u < 1024; u += THREADS) {
        int row = u >> 7, f4 = u & 127;
        float4 v = gc4[row * 128 + f4];
        *reinterpret_cast<float4*>(&cs[row * CPAD + f4 * 4]) = v;
    }

    // ---- deterministic scan: samples in this chunk with label==cls ----
    for (int g = warp; g < 16; g += NWARPS) {
        int idx = base_b + g * 32 + lane;
        unsigned bal = __ballot_sync(0xFFFFFFFFu, labels[idx] == cls);
        if (lane == 0) gmask[g] = bal;
    }
    __syncthreads();
    if (warp == 0 && lane < 16) {
        int cnt = __popc(gmask[lane]);
        int inc = cnt;
#pragma unroll
        for (int off = 1; off < 16; off <<= 1) {
            int o = __shfl_up_sync(0x0000FFFFu, inc, off);
            if (lane >= off) inc += o;
        }
        gbase[lane] = inc - cnt;
        if (lane == 15) s_n = inc;
    }
    __syncthreads();
    for (int g = warp; g < 16; g += NWARPS) {
        unsigned m = gmask[g];
        if ((m >> lane) & 1u)
            list[gbase[g] + __popc(m & ((1u << lane) - 1u))] = g * 32 + lane;
    }
    __syncthreads();

    const int n      = s_n;
    const int rounds = (n + NS - 1) / NS;

    const int group = lane >> 4;            // 0/1 within warp
    const int g_id  = warp * 2 + group;     // 0..5
    const int k     = (lane >> 1) & 7;
    const int h     = lane & 1;
    const int gl    = lane & 16;            // group leader lane

    const float* cb = &cs[k * CPAD + h * 4];
    double bsum = 0.0;

    for (int r = 0; r < rounds; ++r) {
        if (r > 0) __syncthreads();          // xsm reuse protection

        // ---- stage this round's x rows (bulk, coalesced, high MLP) ----
        const int ns = min(NS, n - r * NS);
        for (int u = tid; u < ns * 128; u += THREADS) {
            int slot = u >> 7, f4 = u & 127;
            int b = base_b + list[r * NS + slot];
            const float4* __restrict__ x4 =
                reinterpret_cast<const float4*>(x + (size_t)b * 512);
            *reinterpret_cast<float4*>(&xsm[slot * XPAD + f4 * 4]) = x4[f4];
        }
        __syncthreads();

        // ---- compute: this warp's 4 samples (2 groups x S=2), barrier-free ----
        if (r * NS + 4 * warp < n) {
            const int si0 = r * NS + 2 * g_id;
            const int si1 = si0 + 1;
            const bool a0 = (si0 < n);
            const bool a1 = (si1 < n);
            const int sl0 = a0 ? (2 * g_id)     : 0;
            const int sl1 = a1 ? (2 * g_id + 1) : 0;
            const float* xb0 = &xsm[sl0 * XPAD + h * 4];
            const float* xb1 = &xsm[sl1 * XPAD + h * 4];

            float4 acc0 = make_float4(0.f, 0.f, 0.f, 0.f);
            float4 acc1 = make_float4(0.f, 0.f, 0.f, 0.f);
#pragma unroll 16
            for (int i = 0; i < 64; ++i) {
                float4 cv = *reinterpret_cast<const float4*>(cb + i * 8);
                float4 x0 = *reinterpret_cast<const float4*>(xb0 + i * 8);
                float4 x1 = *reinterpret_cast<const float4*>(xb1 + i * 8);
                acc0.x = fmaf(x0.x, cv.x, acc0.x);
                acc0.y = fmaf(x0.y, cv.y, acc0.y);
                acc0.z = fmaf(x0.z, cv.z, acc0.z);
                acc0.w = fmaf(x0.w, cv.w, acc0.w);
                acc1.x = fmaf(x1.x, cv.x, acc1.x);
                acc1.y = fmaf(x1.y, cv.y, acc1.y);
                acc1.z = fmaf(x1.z, cv.z, acc1.z);
                acc1.w = fmaf(x1.w, cv.w, acc1.w);
            }

            float d0, d1;
            {
                float px = __shfl_xor_sync(0xFFFFFFFFu, acc0.x, 1);
                float py = __shfl_xor_sync(0xFFFFFFFFu, acc0.y, 1);
                float pz = __shfl_xor_sync(0xFFFFFFFFu, acc0.z, 1);
                float pw = __shfl_xor_sync(0xFFFFFFFFu, acc0.w, 1);
                float v0 = __fadd_rn(acc0.x, px);
                float v1 = __fadd_rn(acc0.y, py);
                float v2 = __fadd_rn(acc0.z, pz);
                float v3 = __fadd_rn(acc0.w, pw);
                d0 = __fadd_rn(1.0f, __fadd_rn(__fadd_rn(v0, v1), __fadd_rn(v2, v3)));
            }
            {
                float px = __shfl_xor_sync(0xFFFFFFFFu, acc1.x, 1);
                float py = __shfl_xor_sync(0xFFFFFFFFu, acc1.y, 1);
                float pz = __shfl_xor_sync(0xFFFFFFFFu, acc1.z, 1);
                float pw = __shfl_xor_sync(0xFFFFFFFFu, acc1.w, 1);
                float v0 = __fadd_rn(acc1.x, px);
                float v1 = __fadd_rn(acc1.y, py);
                float v2 = __fadd_rn(acc1.z, pz);
                float v3 = __fadd_rn(acc1.w, pw);
                d1 = __fadd_rn(1.0f, __fadd_rn(__fadd_rn(v0, v1), __fadd_rn(v2, v3)));
            }

            float dl0[8], dl1[8];
#pragma unroll
            for (int j = 0; j < 8; ++j) {
                dl0[j] = __shfl_sync(0xFFFFFFFFu, d0, gl + 2 * j);
                dl1[j] = __shfl_sync(0xFFFFFFFFu, d1, gl + 2 * j);
            }
            float s1a = dl0[0], s1b = dl1[0];
#pragma unroll
            for (int j = 1; j < 8; ++j) {
                s1a = __fadd_rn(s1a, dl0[j]);
                s1b = __fadd_rn(s1b, dl1[j]);
            }
            float wa = 0.f, wb = 0.f;
#pragma unroll
            for (int j = 0; j < 8; ++j) {
                wa = __fadd_rn(wa, __fmul_rn(__fdiv_rn(dl0[j], s1a), dl0[j]));
                wb = __fadd_rn(wb, __fmul_rn(__fdiv_rn(dl1[j], s1b), dl1[j]));
            }
            if ((lane & 15) == 0) {
                if (a0) bsum += (double)wa;
                if (a1) bsum += (double)wb;
            }
        }
    }

    // ---- deterministic block reduction (double) ----
#pragma unroll
    for (int m = 16; m >= 1; m >>= 1)
        bsum += __shfl_xor_sync(0xFFFFFFFFu, bsum, m);
    if (lane == 0) red[warp] = bsum;
    __syncthreads();
    if (tid == 0) {
        double t = 0.0;
#pragma unroll
        for (int j = 0; j < NWARPS; ++j) t += red[j];
        g_partials[blockIdx.x] = t;
        __threadfence();
        unsigned old = atomicInc(&g_count, NBLK - 1);   // wraps -> auto reset
        s_last = (old == NBLK - 1);
    }
    __syncthreads();

    // ---- last block folds all partials (fixed order -> deterministic) ----
    if (s_last) {
        double v = 0.0;
        for (int i = tid; i < NBLK; i += THREADS)
            v += __ldcg(&g_partials[i]);
#pragma unroll
        for (int m = 16; m >= 1; m >>= 1)
            v += __shfl_xor_sync(0xFFFFFFFFu, v, m);
        if (lane == 0) red[warp] = v;
        __syncthreads();
        if (tid == 0) {
            double t = 0.0;
#pragma unroll
            for (int j = 0; j < NWARPS; ++j) t += red[j];
            out[0] = (float)(t * (1.0 / 8192.0));
        }
    }
}

extern "C" void kernel_launch(void* const* d_in, const int* in_sizes, int n_in,
                              void* d_out, int out_size)
{
    const float* x       = (const float*)d_in[0];
    const float* centers = (const float*)d_in[1];
    const int*   labels  = (const int*)d_in[2];
    float*       out     = (float*)d_out;

    loss_main<<<NBLK, THREADS>>>(x, centers, labels, out);
}

// round 15
// speedup vs baseline: 1.0597x; 1.0597x over previous
#include <cuda_runtime.h>

// B=8192, D=512, NUM_CLASSES=90, K=8
// Numerics (validated R9+): NEON VF4xIC2 dot structure:
//   8 serial FMA chains, chain j covers elements 8i+j; combine
//   v_e = fadd(chain_e, chain_{e+4}); dot = fadd(fadd(v0,v1),fadd(v2,v3));
//   d = fadd(1,dot). Epilogue f32 per-op rounded, k ascending. Batch sums double.
// R15: R10's measured-fast loss_main VERBATIM + fused last-block reduction
// (single change: removes the 7.2us second launch).

#define NUM_CLASSES 90
#define CHUNKS      16
#define CHUNK_B     512
#define NBLK        (NUM_CLASSES * CHUNKS)   // 1440
#define THREADS     128
#define NWARPS      4
#define SLOTS       8
#define CPAD        520
#define XPAD        520

__device__ double   g_partials[NBLK];
__device__ unsigned g_count = 0;

__global__ __launch_bounds__(THREADS) void loss_main(
    const float* __restrict__ x,
    const float* __restrict__ centers,
    const int* __restrict__ labels,
    float* __restrict__ out)
{
    __shared__ float    cs[8 * CPAD];
    __shared__ float    xsm[SLOTS * XPAD];
    __shared__ int      list[CHUNK_B];
    __shared__ unsigned gmask[16];
    __shared__ int      gbase[16];
    __shared__ int      s_n;
    __shared__ float    dk[SLOTS][8];
    __shared__ double   red[NWARPS];
    __shared__ int      s_last;

    const int tid    = threadIdx.x;
    const int cls    = blockIdx.x / CHUNKS;
    const int chunk  = blockIdx.x % CHUNKS;
    const int base_b = chunk * CHUNK_B;
    const int warp   = tid >> 5;
    const int lane   = tid & 31;

    // ---- stage this class's 8 center rows into padded smem (coalesced) ----
    const float4* __restrict__ gc4 =
        reinterpret_cast<const float4*>(centers + (size_t)cls * 8 * 512);
    for (int u = tid; u < 1024; u += THREADS) {
        int row = u >> 7, f4 = u & 127;
        float4 v = gc4[row * 128 + f4];
        *reinterpret_cast<float4*>(&cs[row * CPAD + f4 * 4]) = v;
    }

    // ---- deterministic scan: find samples in this chunk with label==cls ----
#pragma unroll
    for (int q = 0; q < 4; ++q) {
        int g = warp * 4 + q;                       // 16 groups of 32 labels
        int idx = base_b + g * 32 + lane;
        unsigned bal = __ballot_sync(0xFFFFFFFFu, labels[idx] == cls);
        if (lane == 0) gmask[g] = bal;
    }
    __syncthreads();
    if (warp == 0 && lane < 16) {
        int cnt = __popc(gmask[lane]);
        int inc = cnt;
#pragma unroll
        for (int off = 1; off < 16; off <<= 1) {
            int o = __shfl_up_sync(0x0000FFFFu, inc, off);
            if (lane >= off) inc += o;
        }
        gbase[lane] = inc - cnt;
        if (lane == 15) s_n = inc;
    }
    __syncthreads();
#pragma unroll
    for (int q = 0; q < 4; ++q) {
        int g = warp * 4 + q;
        unsigned m = gmask[g];
        if ((m >> lane) & 1u)
            list[gbase[g] + __popc(m & ((1u << lane) - 1u))] = g * 32 + lane;
    }
    __syncthreads();

    const int n  = s_n;
    const int nr = (n + SLOTS - 1) / SLOTS;
    double bsum = 0.0;

    const int s     = tid >> 4;      // slot 0..7
    const int k     = (tid >> 1) & 7;
    const int h     = tid & 1;       // 0 = chains 8i+0..3, 1 = chains 8i+4..7
    const int tslot = tid & 15;

    for (int r = 0; r < nr; ++r) {
        const int si = r * SLOTS + s;
        // stage x row for this slot (16 threads per slot, coalesced float4)
        if (si < n) {
            int b = base_b + list[si];
            const float4* __restrict__ x4 =
                reinterpret_cast<const float4*>(x + (size_t)b * 512);
#pragma unroll
            for (int v = 0; v < 8; ++v) {
                int f4 = tslot + 16 * v;
                *reinterpret_cast<float4*>(&xsm[s * XPAD + f4 * 4]) = x4[f4];
            }
        }
        __syncthreads();

        // serial packet chain: acc = va (h=0) or vb (h=1), EXACT validated order
        float4 acc = make_float4(0.f, 0.f, 0.f, 0.f);
        const float* xb = &xsm[s * XPAD + h * 4];
        const float* cb = &cs[k * CPAD + h * 4];
#pragma unroll
        for (int i = 0; i < 64; ++i) {
            float4 xv = *reinterpret_cast<const float4*>(xb + i * 8);
            float4 cv = *reinterpret_cast<const float4*>(cb + i * 8);
            acc.x = fmaf(xv.x, cv.x, acc.x);
            acc.y = fmaf(xv.y, cv.y, acc.y);
            acc.z = fmaf(xv.z, cv.z, acc.z);
            acc.w = fmaf(xv.w, cv.w, acc.w);
        }
        // combine with partner chain (h^1); IEEE add is bitwise-commutative
        float px = __shfl_xor_sync(0xFFFFFFFFu, acc.x, 1);
        float py = __shfl_xor_sync(0xFFFFFFFFu, acc.y, 1);
        float pz = __shfl_xor_sync(0xFFFFFFFFu, acc.z, 1);
        float pw = __shfl_xor_sync(0xFFFFFFFFu, acc.w, 1);
        float v0 = __fadd_rn(acc.x, px);
        float v1 = __fadd_rn(acc.y, py);
        float v2 = __fadd_rn(acc.z, pz);
        float v3 = __fadd_rn(acc.w, pw);
        float dot = __fadd_rn(__fadd_rn(v0, v1), __fadd_rn(v2, v3));
        float d = __fadd_rn(1.0f, dot);
        if (h == 0 && si < n) dk[s][k] = d;
        __syncthreads();

        if (tid == 0) {
            int cnt = n - r * SLOTS;
            if (cnt > SLOTS) cnt = SLOTS;
            for (int ss = 0; ss < cnt; ++ss) {
                float dl[8];
#pragma unroll
                for (int j = 0; j < 8; ++j) dl[j] = dk[ss][j];
                float s1 = dl[0];
#pragma unroll
                for (int j = 1; j < 8; ++j) s1 = __fadd_rn(s1, dl[j]);
                float accw = 0.f;
#pragma unroll
                for (int j = 0; j < 8; ++j) {
                    float w = __fdiv_rn(dl[j], s1);
                    float p = __fmul_rn(w, dl[j]);
                    accw = __fadd_rn(accw, p);
                }
                bsum += (double)accw;
            }
        }
        __syncthreads();
    }

    // ---- fused final reduction (the ONLY change vs R10) ----
    if (tid == 0) {
        g_partials[blockIdx.x] = bsum;
        __threadfence();
        unsigned old = atomicInc(&g_count, NBLK - 1);   // wraps to 0 -> auto reset
        s_last = (old == NBLK - 1);
    }
    __syncthreads();

    if (s_last) {
        double v = 0.0;
        for (int i = tid; i < NBLK; i += THREADS)
            v += __ldcg(&g_partials[i]);
#pragma unroll
        for (int m = 16; m >= 1; m >>= 1)
            v += __shfl_xor_sync(0xFFFFFFFFu, v, m);
        if (lane == 0) red[warp] = v;
        __syncthreads();
        if (tid == 0) {
            double t = 0.0;
#pragma unroll
            for (int j = 0; j < NWARPS; ++j) t += red[j];
            out[0] = (float)(t * (1.0 / 8192.0));
        }
    }
}

extern "C" void kernel_launch(void* const* d_in, const int* in_sizes, int n_in,
                              void* d_out, int out_size)
{
    const float* x       = (const float*)d_in[0];
    const float* centers = (const float*)d_in[1];
    const int*   labels  = (const int*)d_in[2];
    float*       out     = (float*)d_out;

    loss_main<<<NBLK, THREADS>>>(x, centers, labels, out);
}

// round 16
// speedup vs baseline: 1.2449x; 1.1747x over previous
#include <cuda_runtime.h>

// B=8192, D=512, NUM_CLASSES=90, K=8
// Numerics (validated R9+): NEON VF4xIC2 dot structure:
//   8 serial FMA chains, chain j covers elements 8i+j; combine
//   v_e = fadd(chain_e, chain_{e+4}); dot = fadd(fadd(v0,v1),fadd(v2,v3));
//   d = fadd(1,dot). Epilogue f32 per-op rounded, k ascending. Batch sums double.
// R16: 256-thread blocks, scan-first + single merged staging burst,
// parallel per-sample epilogue, fused last-block reduction.

#define NUM_CLASSES 90
#define CHUNKS      16
#define CHUNK_B     512
#define NBLK        (NUM_CLASSES * CHUNKS)   // 1440
#define THREADS     256
#define NWARPS      8
#define SLOTS       12
#define CPAD        520
#define XPAD        520

__device__ double   g_partials[NBLK];
__device__ unsigned g_count = 0;

__global__ __launch_bounds__(THREADS) void loss_main(
    const float* __restrict__ x,
    const float* __restrict__ centers,
    const int* __restrict__ labels,
    float* __restrict__ out)
{
    __shared__ float    cs[8 * CPAD];          // 16.6 KB
    __shared__ float    xsm[SLOTS * XPAD];     // 25.0 KB
    __shared__ int      list[CHUNK_B];         // 2 KB
    __shared__ unsigned gmask[16];
    __shared__ int      gbase[16];
    __shared__ int      s_n;
    __shared__ float    dk[SLOTS][8];
    __shared__ double   red[NWARPS];
    __shared__ int      s_last;

    const int tid    = threadIdx.x;
    const int cls    = blockIdx.x / CHUNKS;
    const int chunk  = blockIdx.x % CHUNKS;
    const int base_b = chunk * CHUNK_B;
    const int warp   = tid >> 5;
    const int lane   = tid & 31;

    // ---- scan FIRST (needs only labels): find samples with label==cls ----
#pragma unroll
    for (int q = 0; q < 2; ++q) {
        int g = warp * 2 + q;                    // 16 groups of 32 labels
        int idx = base_b + g * 32 + lane;
        unsigned bal = __ballot_sync(0xFFFFFFFFu, labels[idx] == cls);
        if (lane == 0) gmask[g] = bal;
    }
    __syncthreads();
    if (warp == 0 && lane < 16) {
        int cnt = __popc(gmask[lane]);
        int inc = cnt;
#pragma unroll
        for (int off = 1; off < 16; off <<= 1) {
            int o = __shfl_up_sync(0x0000FFFFu, inc, off);
            if (lane >= off) inc += o;
        }
        gbase[lane] = inc - cnt;
        if (lane == 15) s_n = inc;
    }
    __syncthreads();
#pragma unroll
    for (int q = 0; q < 2; ++q) {
        int g = warp * 2 + q;
        unsigned m = gmask[g];
        if ((m >> lane) & 1u)
            list[gbase[g] + __popc(m & ((1u << lane) - 1u))] = g * 32 + lane;
    }
    __syncthreads();

    const int n   = s_n;
    const int nr  = (n + SLOTS - 1) / SLOTS;
    const int ns0 = min(n, SLOTS);

    // ---- ONE merged staging burst: centers (1024 f4) + round-0 x rows ----
    const float4* __restrict__ gc4 =
        reinterpret_cast<const float4*>(centers + (size_t)cls * 8 * 512);
    const int total_f4 = 1024 + ns0 * 128;
    for (int u = tid; u < total_f4; u += THREADS) {
        if (u < 1024) {
            int row = u >> 7, f4 = u & 127;
            float4 v = gc4[row * 128 + f4];
            *reinterpret_cast<float4*>(&cs[row * CPAD + f4 * 4]) = v;
        } else {
            int v2 = u - 1024;
            int slot = v2 >> 7, f4 = v2 & 127;
            int b = base_b + list[slot];
            const float4* __restrict__ x4 =
                reinterpret_cast<const float4*>(x + (size_t)b * 512);
            *reinterpret_cast<float4*>(&xsm[slot * XPAD + f4 * 4]) = x4[f4];
        }
    }
    __syncthreads();

    double bsum = 0.0;

    const int s = tid >> 4;          // slot position 0..15 (12..15 idle in chain)
    const int k = (tid >> 1) & 7;
    const int h = tid & 1;           // 0 = chains 8i+0..3, 1 = chains 8i+4..7

    for (int r = 0; r < nr; ++r) {
        if (r > 0) {
            __syncthreads();         // protect xsm before restage
            const int nsr = min(n - r * SLOTS, SLOTS);
            for (int u = tid; u < nsr * 128; u += THREADS) {
                int slot = u >> 7, f4 = u & 127;
                int b = base_b + list[r * SLOTS + slot];
                const float4* __restrict__ x4 =
                    reinterpret_cast<const float4*>(x + (size_t)b * 512);
                *reinterpret_cast<float4*>(&xsm[slot * XPAD + f4 * 4]) = x4[f4];
            }
            __syncthreads();
        }

        // chain: warp w covers slots 2w, 2w+1 (warp-uniform activity guard)
        if (warp < 6 && r * SLOTS + 2 * warp < n) {
            const int si = r * SLOTS + s;
            float4 acc = make_float4(0.f, 0.f, 0.f, 0.f);
            const float* xb = &xsm[s * XPAD + h * 4];
            const float* cb = &cs[k * CPAD + h * 4];
#pragma unroll
            for (int i = 0; i < 64; ++i) {
                float4 xv = *reinterpret_cast<const float4*>(xb + i * 8);
                float4 cv = *reinterpret_cast<const float4*>(cb + i * 8);
                acc.x = fmaf(xv.x, cv.x, acc.x);
                acc.y = fmaf(xv.y, cv.y, acc.y);
                acc.z = fmaf(xv.z, cv.z, acc.z);
                acc.w = fmaf(xv.w, cv.w, acc.w);
            }
            // combine partner chain (h^1); IEEE add bitwise-commutative
            float px = __shfl_xor_sync(0xFFFFFFFFu, acc.x, 1);
            float py = __shfl_xor_sync(0xFFFFFFFFu, acc.y, 1);
            float pz = __shfl_xor_sync(0xFFFFFFFFu, acc.z, 1);
            float pw = __shfl_xor_sync(0xFFFFFFFFu, acc.w, 1);
            float v0 = __fadd_rn(acc.x, px);
            float v1 = __fadd_rn(acc.y, py);
            float v2 = __fadd_rn(acc.z, pz);
            float v3 = __fadd_rn(acc.w, pw);
            float dot = __fadd_rn(__fadd_rn(v0, v1), __fadd_rn(v2, v3));
            float d = __fadd_rn(1.0f, dot);
            if (h == 0 && si < n) dk[s][k] = d;
        }
        __syncthreads();

        // parallel per-sample epilogue (exact validated f32 op order)
        int cnt = n - r * SLOTS;
        if (cnt > SLOTS) cnt = SLOTS;
        if (tid < cnt) {
            float dl[8];
#pragma unroll
            for (int j = 0; j < 8; ++j) dl[j] = dk[tid][j];
            float s1 = dl[0];
#pragma unroll
            for (int j = 1; j < 8; ++j) s1 = __fadd_rn(s1, dl[j]);
            float accw = 0.f;
#pragma unroll
            for (int j = 0; j < 8; ++j) {
                float w = __fdiv_rn(dl[j], s1);
                float p = __fmul_rn(w, dl[j]);
                accw = __fadd_rn(accw, p);
            }
            bsum += (double)accw;
        }
    }

    // ---- deterministic block reduction of bsum (double) ----
#pragma unroll
    for (int m = 16; m >= 1; m >>= 1)
        bsum += __shfl_xor_sync(0xFFFFFFFFu, bsum, m);
    if (lane == 0) red[warp] = bsum;
    __syncthreads();
    if (tid == 0) {
        double t = 0.0;
#pragma unroll
        for (int j = 0; j < NWARPS; ++j) t += red[j];
        g_partials[blockIdx.x] = t;
        __threadfence();
        unsigned old = atomicInc(&g_count, NBLK - 1);   // wraps -> auto reset
        s_last = (old == NBLK - 1);
    }
    __syncthreads();

    // ---- last block folds all partials (fixed order -> deterministic) ----
    if (s_last) {
        double v = 0.0;
        for (int i = tid; i < NBLK; i += THREADS)
            v += __ldcg(&g_partials[i]);
#pragma unroll
        for (int m = 16; m >= 1; m >>= 1)
            v += __shfl_xor_sync(0xFFFFFFFFu, v, m);
        if (lane == 0) red[warp] = v;
        __syncthreads();
        if (tid == 0) {
            double t = 0.0;
#pragma unroll
            for (int j = 0; j < NWARPS; ++j) t += red[j];
            out[0] = (float)(t * (1.0 / 8192.0));
        }
    }
}

extern "C" void kernel_launch(void* const* d_in, const int* in_sizes, int n_in,
                              void* d_out, int out_size)
{
    const float* x       = (const float*)d_in[0];
    const float* centers = (const float*)d_in[1];
    const int*   labels  = (const int*)d_in[2];
    float*       out     = (float*)d_out;

    loss_main<<<NBLK, THREADS>>>(x, centers, labels, out);
}